// round 4
// baseline (speedup 1.0000x reference)
#include <cuda_runtime.h>
#include <cstdint>

// Problem constants (B=2, S=256, H=1024, V=131072, C=512, TOP_K=2)
#define NT   512      // B*S tokens
#define HD   1024     // hidden
#define NC   512      // centroids
#define NV   131072   // vocab
#define VPC  256      // vocab per centroid = NV/NC
#define TOPK 2
#define SPLIT 4       // row-split of each cluster in k_gather

// ---- scratch (no allocations allowed) ----
__device__ float    g_lg[NT * NC];           // routing logits [t][c]
__device__ int      g_top2[NT * TOPK];       // top-2 cluster ids per token
__device__ int      g_count[NC];             // tokens routed to each cluster
__device__ int      g_list[NC * NT];         // packed (token<<1)|k per cluster
__device__ float    g_sel[NT * TOPK * VPC];  // selected logits [t][k][r]
__device__ unsigned g_minkey;                // order-preserving-encoded global min

// order-preserving float<->uint mapping (monotone for unsigned compare)
__device__ __forceinline__ unsigned enc_f(float f) {
    unsigned u = __float_as_uint(f);
    return (u & 0x80000000u) ? ~u : (u | 0x80000000u);
}
__device__ __forceinline__ float dec_f(unsigned u) {
    return __uint_as_float((u & 0x80000000u) ? (u ^ 0x80000000u) : ~u);
}

// ---------------------------------------------------------------------------
// K0: zero counters, init min
// ---------------------------------------------------------------------------
__global__ void k_init() {
    int i = blockIdx.x * blockDim.x + threadIdx.x;
    if (i < NC) g_count[i] = 0;
    if (i == 0) g_minkey = 0xFFFFFFFFu;
}

// ---------------------------------------------------------------------------
// K1a: routing logits GEMM  g_lg[t][c] = <hs[t], cw[c]>
// ---------------------------------------------------------------------------
#define KC 64
__global__ void __launch_bounds__(256) k_logits(const float* __restrict__ hs,
                                                const float* __restrict__ cw) {
    __shared__ float As[32][KC + 1];
    __shared__ float Bs[32][KC + 1];
    int bx = blockIdx.x;              // centroid tile
    int by = blockIdx.y;              // token tile
    int tid = threadIdx.x;
    int tx = tid & 15, ty = tid >> 4;

    float acc00 = 0.f, acc01 = 0.f, acc10 = 0.f, acc11 = 0.f;

    for (int kc = 0; kc < HD; kc += KC) {
        __syncthreads();
        #pragma unroll
        for (int l = tid; l < 512; l += 256) {
            int row = l >> 4, kq = (l & 15) << 2;
            float4 a = *reinterpret_cast<const float4*>(
                &hs[(size_t)(by * 32 + row) * HD + kc + kq]);
            As[row][kq] = a.x; As[row][kq + 1] = a.y;
            As[row][kq + 2] = a.z; As[row][kq + 3] = a.w;
            float4 b = *reinterpret_cast<const float4*>(
                &cw[(size_t)(bx * 32 + row) * HD + kc + kq]);
            Bs[row][kq] = b.x; Bs[row][kq + 1] = b.y;
            Bs[row][kq + 2] = b.z; Bs[row][kq + 3] = b.w;
        }
        __syncthreads();
        #pragma unroll
        for (int kk = 0; kk < KC; kk++) {
            float a0 = As[ty * 2][kk],     a1 = As[ty * 2 + 1][kk];
            float b0 = Bs[tx * 2][kk],     b1 = Bs[tx * 2 + 1][kk];
            acc00 += b0 * a0; acc01 += b0 * a1;
            acc10 += b1 * a0; acc11 += b1 * a1;
        }
    }
    int t = by * 32 + ty * 2, c = bx * 32 + tx * 2;
    g_lg[(size_t)t * NC + c]            = acc00;
    g_lg[(size_t)t * NC + c + 1]        = acc10;
    g_lg[(size_t)(t + 1) * NC + c]      = acc01;
    g_lg[(size_t)(t + 1) * NC + c + 1]  = acc11;
}

// ---------------------------------------------------------------------------
// K1b: top-2 per token + build per-cluster token lists. warp per token.
// ---------------------------------------------------------------------------
__global__ void __launch_bounds__(256) k_top2() {
    int warp = threadIdx.x >> 5, lane = threadIdx.x & 31;
    int t = blockIdx.x * 8 + warp;
    const float* row = g_lg + (size_t)t * NC;

    float bv = -__int_as_float(0x7f800000);
    int   bi = 0x7FFFFFFF;
    for (int c = lane; c < NC; c += 32) {
        float v = row[c];
        if (v > bv || (v == bv && c < bi)) { bv = v; bi = c; }
    }
    #pragma unroll
    for (int o = 16; o; o >>= 1) {
        float ov = __shfl_xor_sync(0xFFFFFFFFu, bv, o);
        int   oi = __shfl_xor_sync(0xFFFFFFFFu, bi, o);
        if (ov > bv || (ov == bv && oi < bi)) { bv = ov; bi = oi; }
    }
    int i0 = bi;
    bv = -__int_as_float(0x7f800000);
    bi = 0x7FFFFFFF;
    for (int c = lane; c < NC; c += 32) {
        if (c == i0) continue;
        float v = row[c];
        if (v > bv || (v == bv && c < bi)) { bv = v; bi = c; }
    }
    #pragma unroll
    for (int o = 16; o; o >>= 1) {
        float ov = __shfl_xor_sync(0xFFFFFFFFu, bv, o);
        int   oi = __shfl_xor_sync(0xFFFFFFFFu, bi, o);
        if (ov > bv || (ov == bv && oi < bi)) { bv = ov; bi = oi; }
    }
    int i1 = bi;

    if (lane == 0) {
        g_top2[t * 2 + 0] = i0;
        g_top2[t * 2 + 1] = i1;
        int p0 = atomicAdd(&g_count[i0], 1);
        g_list[i0 * NT + p0] = (t << 1);
        int p1 = atomicAdd(&g_count[i1], 1);
        g_list[i1 * NT + p1] = (t << 1) | 1;
    }
}

// ---------------------------------------------------------------------------
// K2: cluster-major candidate logits, low-register streaming form.
// Per W-row chunk: load float4, FMA immediately into E per-token accumulators.
// E templated (2/4/8) to bound wasted FLOPs at small token counts.
// ---------------------------------------------------------------------------
#define TCH 8

template <int E>
__device__ __forceinline__ void row_dots(
    const float4* __restrict__ wr, const float4 (*hsm)[HD / 4],
    int lane, int ncur, const int* meta, int r, unsigned& lmin) {
    float acc[E];
    #pragma unroll
    for (int e = 0; e < E; e++) acc[e] = 0.f;
    #pragma unroll
    for (int q = 0; q < 8; q++) {
        float4 w = wr[lane + 32 * q];
        #pragma unroll
        for (int e = 0; e < E; e++) {
            float4 hv = hsm[e][lane + 32 * q];
            acc[e] += w.x * hv.x + w.y * hv.y + w.z * hv.z + w.w * hv.w;
        }
    }
    #pragma unroll
    for (int e = 0; e < E; e++) {
        float p = acc[e];
        #pragma unroll
        for (int o = 16; o; o >>= 1) p += __shfl_xor_sync(0xFFFFFFFFu, p, o);
        if (lane == 0 && e < ncur) {
            int pk = meta[e];
            int t = pk >> 1, k = pk & 1;
            g_sel[(size_t)t * (TOPK * VPC) + k * VPC + r] = p;
            unsigned key = enc_f(p);
            if (key < lmin) lmin = key;
        }
    }
}

__global__ void __launch_bounds__(256) k_gather(const float* __restrict__ hs,
                                                const float* __restrict__ W,
                                                const int* __restrict__ ordering) {
    int c = blockIdx.x;
    int n = g_count[c];
    if (n == 0) return;
    int r0 = blockIdx.y * (VPC / SPLIT);

    __shared__ float4 hsm[TCH][HD / 4];  // 32 KB (zero garbage for unused slots
    __shared__ int    meta[TCH];         //  avoided by templated E rounding)
    __shared__ unsigned s_min[8];

    int tid = threadIdx.x, warp = tid >> 5, lane = tid & 31;
    unsigned lmin = 0xFFFFFFFFu;

    for (int t0 = 0; t0 < n; t0 += TCH) {
        int ncur = min(TCH, n - t0);
        __syncthreads();
        for (int e = tid; e < ncur * (HD / 4); e += 256) {
            int tt = e >> 8, j = e & 255;
            int pk = g_list[c * NT + t0 + tt];
            hsm[tt][j] = reinterpret_cast<const float4*>(hs)[(size_t)(pk >> 1) * (HD / 4) + j];
        }
        if (tid < ncur) meta[tid] = g_list[c * NT + t0 + tid];
        __syncthreads();

        if (ncur <= 2) {
            for (int r = r0 + warp; r < r0 + VPC / SPLIT; r += 8) {
                int vocab = __ldg(&ordering[c * VPC + r]);
                row_dots<2>(reinterpret_cast<const float4*>(W + (size_t)vocab * HD),
                            hsm, lane, ncur, meta, r, lmin);
            }
        } else if (ncur <= 4) {
            for (int r = r0 + warp; r < r0 + VPC / SPLIT; r += 8) {
                int vocab = __ldg(&ordering[c * VPC + r]);
                row_dots<4>(reinterpret_cast<const float4*>(W + (size_t)vocab * HD),
                            hsm, lane, ncur, meta, r, lmin);
            }
        } else {
            for (int r = r0 + warp; r < r0 + VPC / SPLIT; r += 8) {
                int vocab = __ldg(&ordering[c * VPC + r]);
                row_dots<8>(reinterpret_cast<const float4*>(W + (size_t)vocab * HD),
                            hsm, lane, ncur, meta, r, lmin);
            }
        }
    }

    #pragma unroll
    for (int o = 16; o; o >>= 1) {
        unsigned ov = __shfl_xor_sync(0xFFFFFFFFu, lmin, o);
        if (ov < lmin) lmin = ov;
    }
    if (lane == 0) s_min[warp] = lmin;
    __syncthreads();
    if (tid == 0) {
        unsigned m = s_min[0];
        #pragma unroll
        for (int w = 1; w < 8; w++) m = min(m, s_min[w]);
        atomicMin(&g_minkey, m);
    }
}

// ---------------------------------------------------------------------------
// K3a: pure streaming mask fill with write-through (streaming) stores.
// ---------------------------------------------------------------------------
__global__ void __launch_bounds__(256) k_fillmask(float4* __restrict__ out) {
    __shared__ float s_mask;
    if (threadIdx.x == 0) s_mask = dec_f(g_minkey) - 1.0f;
    __syncthreads();
    float m = s_mask;
    float4 mv = make_float4(m, m, m, m);
    size_t base = (size_t)blockIdx.x * 1024 + threadIdx.x;
    #pragma unroll
    for (int j = 0; j < 4; j++) __stwt(&out[base + j * 256], mv);
}

// ---------------------------------------------------------------------------
// K3b: scatter candidate logits over the mask. One block per token,
// 512 threads = (k,r).
// ---------------------------------------------------------------------------
__global__ void __launch_bounds__(512) k_scatter(float* __restrict__ out,
                                                 const int* __restrict__ ordering) {
    int t = blockIdx.x;
    int tid = threadIdx.x;          // = k*256 + r
    int k = tid >> 8, r = tid & 255;
    int c = g_top2[t * 2 + k];
    int v = __ldg(&ordering[c * VPC + r]);
    out[(size_t)t * NV + v] = g_sel[(size_t)t * (TOPK * VPC) + tid];
}

// ---------------------------------------------------------------------------
extern "C" void kernel_launch(void* const* d_in, const int* in_sizes, int n_in,
                              void* d_out, int out_size) {
    const float* hs = (const float*)d_in[0];  // [2,256,1024]
    const float* W  = (const float*)d_in[1];  // [131072,1024]
    const float* cw = (const float*)d_in[2];  // [512,1024]
    const int*   to = (const int*)d_in[3];    // [131072]
    float* out = (float*)d_out;               // [2,256,131072]

    k_init<<<2, 256>>>();
    k_logits<<<dim3(NC / 32, NT / 32), 256>>>(hs, cw);
    k_top2<<<NT / 8, 256>>>();
    k_gather<<<dim3(NC, SPLIT), 256>>>(hs, W, to);
    k_fillmask<<<(unsigned)((size_t)NT * NV / 4 / 1024), 256>>>((float4*)out);
    k_scatter<<<NT, 512>>>(out, to);
}

// round 5
// speedup vs baseline: 1.1763x; 1.1763x over previous
#include <cuda_runtime.h>
#include <cstdint>

// Problem constants (B=2, S=256, H=1024, V=131072, C=512, TOP_K=2)
#define NT   512      // B*S tokens
#define HD   1024     // hidden
#define NC   512      // centroids
#define NV   131072   // vocab
#define VPC  256      // vocab per centroid = NV/NC
#define TOPK 2
#define SPLIT 8       // row-split of each cluster in k_gather (32 rows/block)

// ---- scratch (no allocations allowed) ----
__device__ float    g_lg[NT * NC];           // routing logits [t][c]
__device__ int      g_top2[NT * TOPK];       // top-2 cluster ids per token
__device__ int      g_count[NC];             // tokens routed to each cluster
__device__ int      g_list[NC * NT];         // packed (token<<1)|k per cluster
__device__ float    g_sel[NT * TOPK * VPC];  // selected logits [t][k][r]
__device__ unsigned g_minkey;                // order-preserving-encoded global min

// order-preserving float<->uint mapping (monotone for unsigned compare)
__device__ __forceinline__ unsigned enc_f(float f) {
    unsigned u = __float_as_uint(f);
    return (u & 0x80000000u) ? ~u : (u | 0x80000000u);
}
__device__ __forceinline__ float dec_f(unsigned u) {
    return __uint_as_float((u & 0x80000000u) ? (u ^ 0x80000000u) : ~u);
}

// ---------------------------------------------------------------------------
// K0: zero counters, init min
// ---------------------------------------------------------------------------
__global__ void k_init() {
    int i = blockIdx.x * blockDim.x + threadIdx.x;
    if (i < NC) g_count[i] = 0;
    if (i == 0) g_minkey = 0xFFFFFFFFu;
}

// ---------------------------------------------------------------------------
// K1a: routing logits GEMM  g_lg[t][c] = <hs[t], cw[c]>
// ---------------------------------------------------------------------------
#define KC 64
__global__ void __launch_bounds__(256) k_logits(const float* __restrict__ hs,
                                                const float* __restrict__ cw) {
    __shared__ float As[32][KC + 1];
    __shared__ float Bs[32][KC + 1];
    int bx = blockIdx.x;              // centroid tile
    int by = blockIdx.y;              // token tile
    int tid = threadIdx.x;
    int tx = tid & 15, ty = tid >> 4;

    float acc00 = 0.f, acc01 = 0.f, acc10 = 0.f, acc11 = 0.f;

    for (int kc = 0; kc < HD; kc += KC) {
        __syncthreads();
        #pragma unroll
        for (int l = tid; l < 512; l += 256) {
            int row = l >> 4, kq = (l & 15) << 2;
            float4 a = *reinterpret_cast<const float4*>(
                &hs[(size_t)(by * 32 + row) * HD + kc + kq]);
            As[row][kq] = a.x; As[row][kq + 1] = a.y;
            As[row][kq + 2] = a.z; As[row][kq + 3] = a.w;
            float4 b = *reinterpret_cast<const float4*>(
                &cw[(size_t)(bx * 32 + row) * HD + kc + kq]);
            Bs[row][kq] = b.x; Bs[row][kq + 1] = b.y;
            Bs[row][kq + 2] = b.z; Bs[row][kq + 3] = b.w;
        }
        __syncthreads();
        #pragma unroll
        for (int kk = 0; kk < KC; kk++) {
            float a0 = As[ty * 2][kk],     a1 = As[ty * 2 + 1][kk];
            float b0 = Bs[tx * 2][kk],     b1 = Bs[tx * 2 + 1][kk];
            acc00 += b0 * a0; acc01 += b0 * a1;
            acc10 += b1 * a0; acc11 += b1 * a1;
        }
    }
    int t = by * 32 + ty * 2, c = bx * 32 + tx * 2;
    g_lg[(size_t)t * NC + c]            = acc00;
    g_lg[(size_t)t * NC + c + 1]        = acc10;
    g_lg[(size_t)(t + 1) * NC + c]      = acc01;
    g_lg[(size_t)(t + 1) * NC + c + 1]  = acc11;
}

// ---------------------------------------------------------------------------
// K1b: top-2 per token + build per-cluster token lists. warp per token.
// ---------------------------------------------------------------------------
__global__ void __launch_bounds__(256) k_top2() {
    int warp = threadIdx.x >> 5, lane = threadIdx.x & 31;
    int t = blockIdx.x * 8 + warp;
    const float* row = g_lg + (size_t)t * NC;

    float bv = -__int_as_float(0x7f800000);
    int   bi = 0x7FFFFFFF;
    for (int c = lane; c < NC; c += 32) {
        float v = row[c];
        if (v > bv || (v == bv && c < bi)) { bv = v; bi = c; }
    }
    #pragma unroll
    for (int o = 16; o; o >>= 1) {
        float ov = __shfl_xor_sync(0xFFFFFFFFu, bv, o);
        int   oi = __shfl_xor_sync(0xFFFFFFFFu, bi, o);
        if (ov > bv || (ov == bv && oi < bi)) { bv = ov; bi = oi; }
    }
    int i0 = bi;
    bv = -__int_as_float(0x7f800000);
    bi = 0x7FFFFFFF;
    for (int c = lane; c < NC; c += 32) {
        if (c == i0) continue;
        float v = row[c];
        if (v > bv || (v == bv && c < bi)) { bv = v; bi = c; }
    }
    #pragma unroll
    for (int o = 16; o; o >>= 1) {
        float ov = __shfl_xor_sync(0xFFFFFFFFu, bv, o);
        int   oi = __shfl_xor_sync(0xFFFFFFFFu, bi, o);
        if (ov > bv || (ov == bv && oi < bi)) { bv = ov; bi = oi; }
    }
    int i1 = bi;

    if (lane == 0) {
        g_top2[t * 2 + 0] = i0;
        g_top2[t * 2 + 1] = i1;
        int p0 = atomicAdd(&g_count[i0], 1);
        g_list[i0 * NT + p0] = (t << 1);
        int p1 = atomicAdd(&g_count[i1], 1);
        g_list[i1 * NT + p1] = (t << 1) | 1;
    }
}

// ---------------------------------------------------------------------------
// K2: cluster-major candidate logits. 128 threads (4 warps), 32-row slice.
// Each warp caches TWO W rows in registers via 16 front-batched LDG.128
// (__ldcs: single-use data), then loops routed tokens from smem: one LDS
// feeds both rows; two interleaved shfl reduction trees; float2 result store.
// ---------------------------------------------------------------------------
#define TCH 8
__global__ void __launch_bounds__(128) k_gather(const float* __restrict__ hs,
                                                const float* __restrict__ W,
                                                const int* __restrict__ ordering) {
    int c = blockIdx.x;
    int n = g_count[c];
    if (n == 0) return;
    int r0 = blockIdx.y * (VPC / SPLIT);   // 32-row slice

    __shared__ float4 hsm[TCH][HD / 4];    // 32 KB
    __shared__ int    meta[TCH];
    __shared__ unsigned s_min[4];

    int tid = threadIdx.x, warp = tid >> 5, lane = tid & 31;
    unsigned lmin = 0xFFFFFFFFu;

    for (int t0 = 0; t0 < n; t0 += TCH) {
        int ncur = min(TCH, n - t0);
        __syncthreads();
        for (int e = tid; e < ncur * (HD / 4); e += 128) {
            int tt = e >> 8, j = e & 255;
            int pk = g_list[c * NT + t0 + tt];
            hsm[tt][j] = reinterpret_cast<const float4*>(hs)[(size_t)(pk >> 1) * (HD / 4) + j];
        }
        if (tid < ncur) meta[tid] = g_list[c * NT + t0 + tid];
        __syncthreads();

        // 4 warps x 2 consecutive rows per iteration over the 32-row slice
        #pragma unroll 1
        for (int it = 0; it < (VPC / SPLIT) / 8; it++) {
            int r = r0 + warp * 2 + it * 8;
            int vocab0 = __ldg(&ordering[c * VPC + r]);
            int vocab1 = __ldg(&ordering[c * VPC + r + 1]);
            const float4* wr0 = reinterpret_cast<const float4*>(W + (size_t)vocab0 * HD);
            const float4* wr1 = reinterpret_cast<const float4*>(W + (size_t)vocab1 * HD);
            float4 rv0[8], rv1[8];
            #pragma unroll
            for (int q = 0; q < 8; q++) rv0[q] = __ldcs(&wr0[lane + 32 * q]);
            #pragma unroll
            for (int q = 0; q < 8; q++) rv1[q] = __ldcs(&wr1[lane + 32 * q]);

            for (int e = 0; e < ncur; e++) {
                float p0 = 0.f, p1 = 0.f;
                #pragma unroll
                for (int q = 0; q < 8; q++) {
                    float4 hv = hsm[e][lane + 32 * q];
                    p0 += rv0[q].x * hv.x + rv0[q].y * hv.y + rv0[q].z * hv.z + rv0[q].w * hv.w;
                    p1 += rv1[q].x * hv.x + rv1[q].y * hv.y + rv1[q].z * hv.z + rv1[q].w * hv.w;
                }
                #pragma unroll
                for (int o = 16; o; o >>= 1) {
                    p0 += __shfl_xor_sync(0xFFFFFFFFu, p0, o);
                    p1 += __shfl_xor_sync(0xFFFFFFFFu, p1, o);
                }
                if (lane == 0) {
                    int pk = meta[e];
                    int t = pk >> 1, k = pk & 1;
                    *reinterpret_cast<float2*>(
                        &g_sel[(size_t)t * (TOPK * VPC) + k * VPC + r]) = make_float2(p0, p1);
                    unsigned k0 = enc_f(p0), k1 = enc_f(p1);
                    unsigned kk = min(k0, k1);
                    if (kk < lmin) lmin = kk;
                }
            }
        }
    }

    #pragma unroll
    for (int o = 16; o; o >>= 1) {
        unsigned ov = __shfl_xor_sync(0xFFFFFFFFu, lmin, o);
        if (ov < lmin) lmin = ov;
    }
    if (lane == 0) s_min[warp] = lmin;
    __syncthreads();
    if (tid == 0) {
        unsigned m = min(min(s_min[0], s_min[1]), min(s_min[2], s_min[3]));
        atomicMin(&g_minkey, m);
    }
}

// ---------------------------------------------------------------------------
// K3a: pure streaming mask fill with write-through (streaming) stores.
// ---------------------------------------------------------------------------
__global__ void __launch_bounds__(256) k_fillmask(float4* __restrict__ out) {
    __shared__ float s_mask;
    if (threadIdx.x == 0) s_mask = dec_f(g_minkey) - 1.0f;
    __syncthreads();
    float m = s_mask;
    float4 mv = make_float4(m, m, m, m);
    size_t base = (size_t)blockIdx.x * 1024 + threadIdx.x;
    #pragma unroll
    for (int j = 0; j < 4; j++) __stwt(&out[base + j * 256], mv);
}

// ---------------------------------------------------------------------------
// K3b: scatter candidate logits over the mask. One block per token,
// 512 threads = (k,r).
// ---------------------------------------------------------------------------
__global__ void __launch_bounds__(512) k_scatter(float* __restrict__ out,
                                                 const int* __restrict__ ordering) {
    int t = blockIdx.x;
    int tid = threadIdx.x;          // = k*256 + r
    int k = tid >> 8, r = tid & 255;
    int c = g_top2[t * 2 + k];
    int v = __ldg(&ordering[c * VPC + r]);
    out[(size_t)t * NV + v] = g_sel[(size_t)t * (TOPK * VPC) + tid];
}

// ---------------------------------------------------------------------------
extern "C" void kernel_launch(void* const* d_in, const int* in_sizes, int n_in,
                              void* d_out, int out_size) {
    const float* hs = (const float*)d_in[0];  // [2,256,1024]
    const float* W  = (const float*)d_in[1];  // [131072,1024]
    const float* cw = (const float*)d_in[2];  // [512,1024]
    const int*   to = (const int*)d_in[3];    // [131072]
    float* out = (float*)d_out;               // [2,256,131072]

    k_init<<<2, 256>>>();
    k_logits<<<dim3(NC / 32, NT / 32), 256>>>(hs, cw);
    k_top2<<<NT / 8, 256>>>();
    k_gather<<<dim3(NC, SPLIT), 128>>>(hs, W, to);
    k_fillmask<<<(unsigned)((size_t)NT * NV / 4 / 1024), 256>>>((float4*)out);
    k_scatter<<<NT, 512>>>(out, to);
}